// round 10
// baseline (speedup 1.0000x reference)
#include <cuda_runtime.h>
#include <cstdint>

// Transducer KD loss prep.
// logits/teacher (N=8,T=200,U=50,V=500) fp32; y (N,U) i32; x_lens,y_lens (N,) i32.
// Output (2, N, T, U, 3) fp32.
//
// One warp per (n,t,u) position, both student+teacher rows (shared mask/y),
// 8 front-batched LDG.128.cs. Front-batching is enforced by DATA DEPENDENCE:
// the exp chain consumes the LAST-loaded vector first, so ptxas gains nothing
// by interleaving MUFU between loads (the R4/R9 collapse) and keeps all 8
// vectors live -> true MLP_p1 = 8. Gather logits re-fetched from L2 by lane 0.

#define TN 8
#define TT 200
#define TU 50
#define TV 500
#define ROWS (TN * TT * TU)     // 80000
#define T_EPS 1e-10f
#define NEG_BIG -1e30f

__global__ void __launch_bounds__(128)
transducer_kd_kernel(const float* __restrict__ logits,
                     const float* __restrict__ teacher,
                     const int*   __restrict__ y,
                     const int*   __restrict__ x_lens,
                     const int*   __restrict__ y_lens,
                     float*       __restrict__ out)
{
    const int warp_global = (int)((blockIdx.x * blockDim.x + threadIdx.x) >> 5);
    const int lane = threadIdx.x & 31;
    if (warp_global >= ROWS) return;

    const int r  = warp_global;
    const int n  = r / (TT * TU);
    const int tu = r - n * (TT * TU);
    const int t  = tu / TU;
    const int u  = tu - t * TU;

    float* os = out + (size_t)r * 3;                 // student triple
    float* ot = out + (size_t)(ROWS + r) * 3;        // teacher triple

    const bool active = (t < x_lens[n]) && (u < y_lens[n]);
    if (!active) {
        if (lane < 3) { os[lane] = 0.0f; ot[lane] = 0.0f; }
        return;
    }

    const float* sbase = logits  + (size_t)r * TV;
    const float* tbase = teacher + (size_t)r * TV;
    const float4* s4 = (const float4*)sbase;
    const float4* t4 = (const float4*)tbase;
    const bool tail = (lane < 29);                   // 125 float4 per row

    // ---- Phase 1: 8 front-batched streaming loads ----
    float4 sv0 = __ldcs(s4 + lane);
    float4 sv1 = __ldcs(s4 + lane + 32);
    float4 sv2 = __ldcs(s4 + lane + 64);
    float4 tv0 = __ldcs(t4 + lane);
    float4 tv1 = __ldcs(t4 + lane + 32);
    float4 tv2 = __ldcs(t4 + lane + 64);
    float4 sv3 = make_float4(NEG_BIG, NEG_BIG, NEG_BIG, NEG_BIG);
    float4 tv3 = make_float4(NEG_BIG, NEG_BIG, NEG_BIG, NEG_BIG);
    if (tail) {
        sv3 = __ldcs(s4 + lane + 96);
        tv3 = __ldcs(t4 + lane + 96);
    }

    // ---- Phase 2: exp + sums, consuming LAST loads FIRST ----
    // First MUFU depends on the final load's scoreboard -> ptxas has no
    // incentive to interleave; all 8 vectors stay live (true front-batch).
    float ta = (__expf(tv3.x) + __expf(tv3.y)) + (__expf(tv3.z) + __expf(tv3.w));
    float sa = (__expf(sv3.x) + __expf(sv3.y)) + (__expf(sv3.z) + __expf(sv3.w));
    ta += (__expf(tv2.x) + __expf(tv2.y)) + (__expf(tv2.z) + __expf(tv2.w));
    sa += (__expf(sv2.x) + __expf(sv2.y)) + (__expf(sv2.z) + __expf(sv2.w));
    ta += (__expf(tv1.x) + __expf(tv1.y)) + (__expf(tv1.z) + __expf(tv1.w));
    sa += (__expf(sv1.x) + __expf(sv1.y)) + (__expf(sv1.z) + __expf(sv1.w));
    ta += (__expf(tv0.x) + __expf(tv0.y)) + (__expf(tv0.z) + __expf(tv0.w));
    sa += (__expf(sv0.x) + __expf(sv0.y)) + (__expf(sv0.z) + __expf(sv0.w));

    #pragma unroll
    for (int off = 16; off > 0; off >>= 1) {
        sa += __shfl_xor_sync(0xFFFFFFFFu, sa, off);
        ta += __shfl_xor_sync(0xFFFFFFFFu, ta, off);
    }

    if (lane == 0) {
        const int yi = __ldg(y + n * TU + u);
        // gathered logits: L2 hits (rows just streamed through L2)
        const float s_ly = __ldg(sbase + yi);
        const float t_ly = __ldg(tbase + yi);
        const float s_lb = __ldg(sbase);
        const float t_lb = __ldg(tbase);

        // student: log(clip(x, EPS, 1))
        const float sinv   = 1.0f / sa;
        const float spy    = __expf(s_ly) * sinv;
        const float sblank = __expf(s_lb) * sinv;
        const float srem   = 1.0f - spy - sblank;
        os[0] = logf(fminf(fmaxf(spy,    T_EPS), 1.0f));
        os[1] = logf(fminf(fmaxf(sblank, T_EPS), 1.0f));
        os[2] = logf(fminf(fmaxf(srem,   T_EPS), 1.0f));
        // teacher: raw probs; rem clamped to EPS if negative
        const float tinv   = 1.0f / ta;
        const float tpy    = __expf(t_ly) * tinv;
        const float tblank = __expf(t_lb) * tinv;
        const float trem   = 1.0f - tpy - tblank;
        ot[0] = tpy;
        ot[1] = tblank;
        ot[2] = (trem < 0.0f) ? T_EPS : trem;
    }
}

extern "C" void kernel_launch(void* const* d_in, const int* in_sizes, int n_in,
                              void* d_out, int out_size)
{
    const float* logits  = (const float*)d_in[0];
    const float* teacher = (const float*)d_in[1];
    const int*   y       = (const int*)d_in[2];
    const int*   x_lens  = (const int*)d_in[3];
    const int*   y_lens  = (const int*)d_in[4];
    float* out = (float*)d_out;

    const int WARPS_PER_BLOCK = 4;          // 128 threads
    const int blocks = (ROWS + WARPS_PER_BLOCK - 1) / WARPS_PER_BLOCK;
    transducer_kd_kernel<<<blocks, WARPS_PER_BLOCK * 32>>>(
        logits, teacher, y, x_lens, y_lens, out);
}

// round 11
// speedup vs baseline: 1.2262x; 1.2262x over previous
#include <cuda_runtime.h>

// Transducer KD loss prep — R3 structure (shfl-extract liveness anchor) at
// 128-thread blocks for higher occupancy.
// logits/teacher (N=8,T=200,U=50,V=500) fp32; y (N,U) i32; x_lens,y_lens (N,) i32.
// Output (2, N, T, U, 3) fp32.
//
// One warp per (n,t,u) position, both student+teacher rows (shared mask/y).
// 8 front-batched LDG.128.cs per lane. The gathered py/blank logits are
// extracted from the loaded registers via shfl — this gives every vector a
// second use that ptxas cannot rematerialize, forcing all 8 to stay live
// (regs~48) and preserving MLP_p1=8 (R4/R9/R10 all collapsed without it).

#define TN 8
#define TT 200
#define TU 50
#define TV 500
#define ROWS (TN * TT * TU)     // 80000
#define T_EPS 1e-10f
#define NEG_BIG -1e30f

__global__ void __launch_bounds__(128)
transducer_kd_kernel(const float* __restrict__ logits,
                     const float* __restrict__ teacher,
                     const int*   __restrict__ y,
                     const int*   __restrict__ x_lens,
                     const int*   __restrict__ y_lens,
                     float*       __restrict__ out)
{
    const int warp_global = (int)((blockIdx.x * blockDim.x + threadIdx.x) >> 5);
    const int lane = threadIdx.x & 31;
    if (warp_global >= ROWS) return;

    const int r  = warp_global;
    const int n  = r / (TT * TU);
    const int tu = r - n * (TT * TU);
    const int t  = tu / TU;
    const int u  = tu - t * TU;

    float* os = out + (size_t)r * 3;                    // student triple
    float* ot = out + (size_t)(ROWS + r) * 3;           // teacher triple

    const bool active = (t < x_lens[n]) && (u < y_lens[n]);
    if (!active) {
        if (lane < 3) { os[lane] = 0.0f; ot[lane] = 0.0f; }
        return;
    }

    const float4* s4 = (const float4*)(logits  + (size_t)r * TV);
    const float4* t4 = (const float4*)(teacher + (size_t)r * TV);
    const bool tail = (lane < 29);            // 125 float4 per row

    // ---- Phase 1: 8 front-batched streaming loads ----
    float4 sv0 = __ldcs(s4 + lane);
    float4 sv1 = __ldcs(s4 + lane + 32);
    float4 sv2 = __ldcs(s4 + lane + 64);
    float4 tv0 = __ldcs(t4 + lane);
    float4 tv1 = __ldcs(t4 + lane + 32);
    float4 tv2 = __ldcs(t4 + lane + 64);
    float4 sv3 = make_float4(NEG_BIG, NEG_BIG, NEG_BIG, NEG_BIG);
    float4 tv3 = make_float4(NEG_BIG, NEG_BIG, NEG_BIG, NEG_BIG);
    if (tail) {
        sv3 = __ldcs(s4 + lane + 96);
        tv3 = __ldcs(t4 + lane + 96);
    }
    const int yi = __ldg(y + n * TU + u);     // uniform across warp

    // ---- Extract py / blank raw logits from registers (liveness anchor) ----
    const int idx4 = yi >> 2;                 // which float4 (0..124)
    const int comp = yi & 3;
    const int src  = idx4 & 31;
    const int grp  = idx4 >> 5;               // 0..3

    float4 svy = (grp == 0) ? sv0 : (grp == 1) ? sv1 : (grp == 2) ? sv2 : sv3;
    float4 tvy = (grp == 0) ? tv0 : (grp == 1) ? tv1 : (grp == 2) ? tv2 : tv3;
    float sx = (comp == 0) ? svy.x : (comp == 1) ? svy.y : (comp == 2) ? svy.z : svy.w;
    float tx = (comp == 0) ? tvy.x : (comp == 1) ? tvy.y : (comp == 2) ? tvy.z : tvy.w;
    const float s_logit_y = __shfl_sync(0xFFFFFFFFu, sx, src);
    const float t_logit_y = __shfl_sync(0xFFFFFFFFu, tx, src);
    const float s_logit_b = __shfl_sync(0xFFFFFFFFu, sv0.x, 0);
    const float t_logit_b = __shfl_sync(0xFFFFFFFFu, tv0.x, 0);

    // ---- Phase 2: exp + tree sums (both rows) ----
    float sa = (__expf(sv0.x) + __expf(sv0.y)) + (__expf(sv0.z) + __expf(sv0.w));
    sa += (__expf(sv1.x) + __expf(sv1.y)) + (__expf(sv1.z) + __expf(sv1.w));
    sa += (__expf(sv2.x) + __expf(sv2.y)) + (__expf(sv2.z) + __expf(sv2.w));
    sa += (__expf(sv3.x) + __expf(sv3.y)) + (__expf(sv3.z) + __expf(sv3.w));
    float ta = (__expf(tv0.x) + __expf(tv0.y)) + (__expf(tv0.z) + __expf(tv0.w));
    ta += (__expf(tv1.x) + __expf(tv1.y)) + (__expf(tv1.z) + __expf(tv1.w));
    ta += (__expf(tv2.x) + __expf(tv2.y)) + (__expf(tv2.z) + __expf(tv2.w));
    ta += (__expf(tv3.x) + __expf(tv3.y)) + (__expf(tv3.z) + __expf(tv3.w));

    #pragma unroll
    for (int off = 16; off > 0; off >>= 1) {
        sa += __shfl_xor_sync(0xFFFFFFFFu, sa, off);
        ta += __shfl_xor_sync(0xFFFFFFFFu, ta, off);
    }

    if (lane == 0) {
        // student: log(clip(x, EPS, 1))
        const float sinv   = 1.0f / sa;
        const float spy    = __expf(s_logit_y) * sinv;
        const float sblank = __expf(s_logit_b) * sinv;
        const float srem   = 1.0f - spy - sblank;
        os[0] = logf(fminf(fmaxf(spy,    T_EPS), 1.0f));
        os[1] = logf(fminf(fmaxf(sblank, T_EPS), 1.0f));
        os[2] = logf(fminf(fmaxf(srem,   T_EPS), 1.0f));
        // teacher: raw probs; rem clamped to EPS if negative
        const float tinv   = 1.0f / ta;
        const float tpy    = __expf(t_logit_y) * tinv;
        const float tblank = __expf(t_logit_b) * tinv;
        const float trem   = 1.0f - tpy - tblank;
        ot[0] = tpy;
        ot[1] = tblank;
        ot[2] = (trem < 0.0f) ? T_EPS : trem;
    }
}

extern "C" void kernel_launch(void* const* d_in, const int* in_sizes, int n_in,
                              void* d_out, int out_size)
{
    const float* logits  = (const float*)d_in[0];
    const float* teacher = (const float*)d_in[1];
    const int*   y       = (const int*)d_in[2];
    const int*   x_lens  = (const int*)d_in[3];
    const int*   y_lens  = (const int*)d_in[4];
    float* out = (float*)d_out;

    const int WARPS_PER_BLOCK = 4;          // 128 threads
    const int blocks = (ROWS + WARPS_PER_BLOCK - 1) / WARPS_PER_BLOCK;
    transducer_kd_kernel<<<blocks, WARPS_PER_BLOCK * 32>>>(
        logits, teacher, y, x_lens, y_lens, out);
}

// round 12
// speedup vs baseline: 1.2400x; 1.0113x over previous
#include <cuda_runtime.h>

// Transducer KD loss prep — R11 (shfl-extract liveness anchor, 128-thr blocks)
// with parallelized fast-math epilogue.
// logits/teacher (N=8,T=200,U=50,V=500) fp32; y (N,U) i32; x_lens,y_lens (N,) i32.
// Output (2, N, T, U, 3) fp32.
//
// One warp per (n,t,u) position, both student+teacher rows (shared mask/y).
// 8 front-batched LDG.128.cs per lane; gathered logits extracted from the
// loaded registers via shfl (second, unrematerializable use -> ptxas keeps
// all 8 vectors live, regs~48, MLP_p1=8). Epilogue: after the xor-reduction
// every lane holds the sums + extracted logits, so all lanes compute the 6
// outputs in parallel (fast __logf / __fdividef) and lanes 0-5 store one each.

#define TN 8
#define TT 200
#define TU 50
#define TV 500
#define ROWS (TN * TT * TU)     // 80000
#define T_EPS 1e-10f
#define NEG_BIG -1e30f

__global__ void __launch_bounds__(128)
transducer_kd_kernel(const float* __restrict__ logits,
                     const float* __restrict__ teacher,
                     const int*   __restrict__ y,
                     const int*   __restrict__ x_lens,
                     const int*   __restrict__ y_lens,
                     float*       __restrict__ out)
{
    const int warp_global = (int)((blockIdx.x * blockDim.x + threadIdx.x) >> 5);
    const int lane = threadIdx.x & 31;
    if (warp_global >= ROWS) return;

    const int r  = warp_global;
    const int n  = r / (TT * TU);
    const int tu = r - n * (TT * TU);
    const int t  = tu / TU;
    const int u  = tu - t * TU;

    float* os = out + (size_t)r * 3;                    // student triple
    float* ot = out + (size_t)(ROWS + r) * 3;           // teacher triple

    const bool active = (t < x_lens[n]) && (u < y_lens[n]);
    if (!active) {
        if (lane < 3) { os[lane] = 0.0f; ot[lane] = 0.0f; }
        return;
    }

    const float4* s4 = (const float4*)(logits  + (size_t)r * TV);
    const float4* t4 = (const float4*)(teacher + (size_t)r * TV);
    const bool tail = (lane < 29);            // 125 float4 per row

    // ---- Phase 1: 8 front-batched streaming loads ----
    float4 sv0 = __ldcs(s4 + lane);
    float4 sv1 = __ldcs(s4 + lane + 32);
    float4 sv2 = __ldcs(s4 + lane + 64);
    float4 tv0 = __ldcs(t4 + lane);
    float4 tv1 = __ldcs(t4 + lane + 32);
    float4 tv2 = __ldcs(t4 + lane + 64);
    float4 sv3 = make_float4(NEG_BIG, NEG_BIG, NEG_BIG, NEG_BIG);
    float4 tv3 = make_float4(NEG_BIG, NEG_BIG, NEG_BIG, NEG_BIG);
    if (tail) {
        sv3 = __ldcs(s4 + lane + 96);
        tv3 = __ldcs(t4 + lane + 96);
    }
    const int yi = __ldg(y + n * TU + u);     // uniform across warp

    // ---- Extract py / blank raw logits from registers (liveness anchor) ----
    const int idx4 = yi >> 2;                 // which float4 (0..124)
    const int comp = yi & 3;
    const int src  = idx4 & 31;
    const int grp  = idx4 >> 5;               // 0..3

    float4 svy = (grp == 0) ? sv0 : (grp == 1) ? sv1 : (grp == 2) ? sv2 : sv3;
    float4 tvy = (grp == 0) ? tv0 : (grp == 1) ? tv1 : (grp == 2) ? tv2 : tv3;
    float sx = (comp == 0) ? svy.x : (comp == 1) ? svy.y : (comp == 2) ? svy.z : svy.w;
    float tx = (comp == 0) ? tvy.x : (comp == 1) ? tvy.y : (comp == 2) ? tvy.z : tvy.w;
    const float s_ly = __shfl_sync(0xFFFFFFFFu, sx, src);
    const float t_ly = __shfl_sync(0xFFFFFFFFu, tx, src);
    const float s_lb = __shfl_sync(0xFFFFFFFFu, sv0.x, 0);
    const float t_lb = __shfl_sync(0xFFFFFFFFu, tv0.x, 0);

    // ---- Phase 2: exp + tree sums (both rows) ----
    float sa = (__expf(sv0.x) + __expf(sv0.y)) + (__expf(sv0.z) + __expf(sv0.w));
    sa += (__expf(sv1.x) + __expf(sv1.y)) + (__expf(sv1.z) + __expf(sv1.w));
    sa += (__expf(sv2.x) + __expf(sv2.y)) + (__expf(sv2.z) + __expf(sv2.w));
    sa += (__expf(sv3.x) + __expf(sv3.y)) + (__expf(sv3.z) + __expf(sv3.w));
    float ta = (__expf(tv0.x) + __expf(tv0.y)) + (__expf(tv0.z) + __expf(tv0.w));
    ta += (__expf(tv1.x) + __expf(tv1.y)) + (__expf(tv1.z) + __expf(tv1.w));
    ta += (__expf(tv2.x) + __expf(tv2.y)) + (__expf(tv2.z) + __expf(tv2.w));
    ta += (__expf(tv3.x) + __expf(tv3.y)) + (__expf(tv3.z) + __expf(tv3.w));

    #pragma unroll
    for (int off = 16; off > 0; off >>= 1) {
        sa += __shfl_xor_sync(0xFFFFFFFFu, sa, off);
        ta += __shfl_xor_sync(0xFFFFFFFFu, ta, off);
    }

    // ---- Epilogue: all lanes compute, lanes 0-5 store one element each ----
    const float sinv   = __fdividef(1.0f, sa);
    const float spy    = __expf(s_ly) * sinv;
    const float sblank = __expf(s_lb) * sinv;
    const float srem   = 1.0f - spy - sblank;
    const float so0 = __logf(fminf(fmaxf(spy,    T_EPS), 1.0f));
    const float so1 = __logf(fminf(fmaxf(sblank, T_EPS), 1.0f));
    const float so2 = __logf(fminf(fmaxf(srem,   T_EPS), 1.0f));

    const float tinv   = __fdividef(1.0f, ta);
    const float tpy    = __expf(t_ly) * tinv;
    const float tblank = __expf(t_lb) * tinv;
    const float trem0  = 1.0f - tpy - tblank;
    const float to2    = (trem0 < 0.0f) ? T_EPS : trem0;

    if (lane < 6) {
        const int c = (lane < 3) ? lane : lane - 3;
        float val;
        if (lane < 3)
            val = (c == 0) ? so0 : (c == 1) ? so1 : so2;
        else
            val = (c == 0) ? tpy : (c == 1) ? tblank : to2;
        float* p = (lane < 3) ? (os + c) : (ot + c);
        *p = val;
    }
}

extern "C" void kernel_launch(void* const* d_in, const int* in_sizes, int n_in,
                              void* d_out, int out_size)
{
    const float* logits  = (const float*)d_in[0];
    const float* teacher = (const float*)d_in[1];
    const int*   y       = (const int*)d_in[2];
    const int*   x_lens  = (const int*)d_in[3];
    const int*   y_lens  = (const int*)d_in[4];
    float* out = (float*)d_out;

    const int WARPS_PER_BLOCK = 4;          // 128 threads
    const int blocks = (ROWS + WARPS_PER_BLOCK - 1) / WARPS_PER_BLOCK;
    transducer_kd_kernel<<<blocks, WARPS_PER_BLOCK * 32>>>(
        logits, teacher, y, x_lens, y_lens, out);
}